// round 15
// baseline (speedup 1.0000x reference)
#include <cuda_runtime.h>

// Fused 6-layer ReLU RNN + FC + log_softmax, diagonal-wavefront persistent kernel.
// R15 = R14 (neuron-duo threads, role split, staged wi partials, broadcast LDS)
//       + steady-state specialization: ticks 14..TT-3 run a guard-free body with
//       compile-time buffer parity (static SMEM offsets, no per-tick pointer
//       math, no branches). Ramp head/tail keep the generic guarded body.
//       NTH=512 (16 warps, 128 regs), grid=128, plain __syncthreads() per tick.

#define TT 1024
#define BB 2048
#define HH 20
#define LL 6
#define ROWS (LL + 1)  // row 0 = x, row l+1 = h_l
#define PP 8           // batch-pairs per CTA (pair = 2 batch elems packed f32x2)
#define PSTR 22        // padded row stride in 8B units (16B-aligned rows)
#define NTH 512
#define NCTA 128
#define NTICK (TT + 13)
#define STEADY_BEG 14
#define STEADY_END 1021   // inclusive; [14,1021] has all guards true, even count

typedef unsigned long long u64;

__device__ __forceinline__ u64 f2fma(u64 a, u64 b, u64 c) {
    u64 r; asm("fma.rn.f32x2 %0, %1, %2, %3;" : "=l"(r) : "l"(a), "l"(b), "l"(c)); return r;
}
__device__ __forceinline__ u64 f2add(u64 a, u64 b) {
    u64 r; asm("add.rn.f32x2 %0, %1, %2;" : "=l"(r) : "l"(a), "l"(b)); return r;
}
__device__ __forceinline__ u64 dup2(float x) {
    u64 r; asm("mov.b64 %0, {%1, %1};" : "=l"(r) : "f"(x)); return r;
}
__device__ __forceinline__ u64 pk2(float lo, float hi) {
    u64 r; asm("mov.b64 %0, {%1, %2};" : "=l"(r) : "f"(lo), "f"(hi)); return r;
}
__device__ __forceinline__ void unpk(u64 a, float& lo, float& hi) {
    asm("mov.b64 {%0, %1}, %2;" : "=f"(lo), "=f"(hi) : "l"(a));
}
__device__ __forceinline__ u64 f2relu(u64 a) {
    float lo, hi; unpk(a, lo, hi);
    return pk2(fmaxf(lo, 0.0f), fmaxf(hi, 0.0f));
}

// Two 20-element f32x2 dots sharing one loaded h-row (neuron duo).
__device__ __forceinline__ void dot20x2(const u64 (&wa)[HH], const u64 (&wb_)[HH],
                                        const u64* hbase, u64 accA, u64 accB,
                                        u64& outA, u64& outB) {
    const ulonglong2* h2 = (const ulonglong2*)hbase;
    u64 aA0 = accA, aA1 = 0ull, aB0 = accB, aB1 = 0ull;
#pragma unroll
    for (int q = 0; q < 10; q++) {
        ulonglong2 hq = h2[q];
        aA0 = f2fma(wa[2 * q],     hq.x, aA0);
        aA1 = f2fma(wa[2 * q + 1], hq.y, aA1);
        aB0 = f2fma(wb_[2 * q],     hq.x, aB0);
        aB1 = f2fma(wb_[2 * q + 1], hq.y, aB1);
    }
    outA = f2add(aA0, aA1);
    outB = f2add(aB0, aB1);
}

// Single 20-element dot (fc lanes).
__device__ __forceinline__ u64 dot20(const u64 (&w)[HH], const u64* hbase, u64 acc) {
    const ulonglong2* h2 = (const ulonglong2*)hbase;
    u64 a0 = acc, a1 = 0ull;
#pragma unroll
    for (int q = 0; q < 10; q++) {
        ulonglong2 hq = h2[q];
        a0 = f2fma(w[2 * q],     hq.x, a0);
        a1 = f2fma(w[2 * q + 1], hq.y, a1);
    }
    return f2add(a0, a1);
}

__global__ __launch_bounds__(NTH, 1) void rnn_wavefront_kernel(
    const float* __restrict__ x,     // [T, B, 2]
    const float* __restrict__ Wih0,  // [H, 2]
    const float* __restrict__ Wih,   // [L-1, H, H]
    const float* __restrict__ Whh,   // [L, H, H]
    const float* __restrict__ bih,   // [L, H]
    const float* __restrict__ bhh,   // [L, H]
    const float* __restrict__ fcw,   // [2, H]
    const float* __restrict__ fcb,   // [2]
    float* __restrict__ out)         // [T, B, 2]
{
    __shared__ __align__(16) u64 hb[2][ROWS][PP * PSTR];  // x + h state, double-buffered
    __shared__ __align__(16) u64 st[2][LL][PP * HH];      // staged wi partials
    __shared__ __align__(16) u64 logitb[2][PP][2];        // logits, double-buffered

    const int tid = threadIdx.x;

    for (int i = tid; i < 2 * ROWS * PP * PSTR; i += NTH) ((u64*)hb)[i] = 0ull;
    for (int i = tid; i < 2 * LL * PP * HH; i += NTH)     ((u64*)st)[i] = 0ull;
    for (int i = tid; i < 2 * PP * 2; i += NTH)           ((u64*)logitb)[i] = 0ull;

    // ---- role decomposition: tid = role*240 + l*40 + pg*10 + jd (0..479) ----
    const bool is_layer = tid < 480;
    const int role = tid / 240;          // 0 = wi-dot (stage), 1 = wh-dot (relu+store)
    const int sub  = tid % 240;
    const int l    = sub / 40;
    const int r2   = sub % 40;
    const int pg   = r2 / 10;            // pair-group 0..3
    const int jd   = r2 % 10;            // neuron duo: j = jd, j+10
    const int p0 = pg, p1 = pg + 4;

    const bool is_fc = (tid >= 480) && (tid < 496);     // fc lanes
    const int fc_p = (tid - 480) >> 1;
    const int fc_c = tid & 1;
    const int sm_p = (tid - 496) >> 1;
    const int sm_w = tid & 1;

    // ---- weights into registers: rows for neurons jd and jd+10 ----
    u64 wA[HH], wB[HH];
    u64 bjA = 0ull, bjB = 0ull;
#pragma unroll
    for (int k = 0; k < HH; k++) { wA[k] = 0ull; wB[k] = 0ull; }

    if (is_layer) {
        if (role == 1) {          // wh: recurrent weights
#pragma unroll
            for (int k = 0; k < HH; k++) {
                wA[k] = dup2(Whh[(l * HH + jd) * HH + k]);
                wB[k] = dup2(Whh[(l * HH + jd + 10) * HH + k]);
            }
        } else if (l > 0) {       // wi: input weights, generic layer
#pragma unroll
            for (int k = 0; k < HH; k++) {
                wA[k] = dup2(Wih[((l - 1) * HH + jd) * HH + k]);
                wB[k] = dup2(Wih[((l - 1) * HH + jd + 10) * HH + k]);
            }
            bjA = dup2(bih[l * HH + jd] + bhh[l * HH + jd]);
            bjB = dup2(bih[l * HH + jd + 10] + bhh[l * HH + jd + 10]);
        } else {                  // wi layer 0: x-projection in slots 0..1
            wA[0] = dup2(Wih0[jd * 2 + 0]);
            wA[1] = dup2(Wih0[jd * 2 + 1]);
            wB[0] = dup2(Wih0[(jd + 10) * 2 + 0]);
            wB[1] = dup2(Wih0[(jd + 10) * 2 + 1]);
            bjA = dup2(bih[jd] + bhh[jd]);
            bjB = dup2(bih[jd + 10] + bhh[jd + 10]);
        }
    } else if (is_fc) {
#pragma unroll
        for (int k = 0; k < HH; k++) wA[k] = dup2(fcw[fc_c * HH + k]);
        bjA = dup2(fcb[fc_c]);
    }

    // ---- x prefetch state (sm lanes; 2-tick register pipeline) ----
    const float* __restrict__ xf = (const float*)x;   // xf[(t*BB + b)*2 + k]
    int xb0 = 0, xb1 = 0;
    float xv0 = 0.0f, xv1 = 0.0f;
    if (tid >= 496) {
        xb0 = blockIdx.x * PP + sm_p;
        xb1 = xb0 + (BB / 2);
        hb[0][0][sm_p * PSTR + sm_w] = pk2(xf[xb0 * 2 + sm_w], xf[xb1 * 2 + sm_w]);
        xv0 = xf[(BB + xb0) * 2 + sm_w];
        xv1 = xf[(BB + xb1) * 2 + sm_w];
    }

    __syncthreads();

    // ---- tick body macro. AA must be a literal in steady calls so hb[AA] /
    //      st[AA] constant-fold to static SMEM offsets. STEADY=true deletes
    //      every guard (provably true for tau in [STEADY_BEG, STEADY_END]). ----
#define TICK(TAUE, AA, STEADY) do {                                             \
        const int tau_ = (TAUE);                                                \
        const u64(*rb)[PP * PSTR] = hb[AA];                                     \
        u64(*wb)[PP * PSTR] = hb[(AA) ^ 1];                                     \
        const u64(*sr)[PP * HH] = st[AA];                                       \
        u64(*sw)[PP * HH] = st[(AA) ^ 1];                                       \
        if (is_layer) {                                                         \
            if (role == 0) {                                                    \
                if (STEADY || (unsigned)(tau_ - 2 * l) < TT) {                  \
                    u64 oA, oB;                                                 \
                    dot20x2(wA, wB, &rb[l][p0 * PSTR], bjA, bjB, oA, oB);       \
                    sw[l][p0 * HH + jd]      = oA;                              \
                    sw[l][p0 * HH + jd + 10] = oB;                              \
                    dot20x2(wA, wB, &rb[l][p1 * PSTR], bjA, bjB, oA, oB);       \
                    sw[l][p1 * HH + jd]      = oA;                              \
                    sw[l][p1 * HH + jd + 10] = oB;                              \
                }                                                               \
            } else {                                                            \
                if (STEADY || (unsigned)(tau_ - 2 * l - 1) < TT) {              \
                    u64 oA, oB;                                                 \
                    dot20x2(wA, wB, &rb[l + 1][p0 * PSTR],                      \
                            sr[l][p0 * HH + jd], sr[l][p0 * HH + jd + 10],      \
                            oA, oB);                                            \
                    wb[l + 1][p0 * PSTR + jd]      = f2relu(oA);                \
                    wb[l + 1][p0 * PSTR + jd + 10] = f2relu(oB);                \
                    dot20x2(wA, wB, &rb[l + 1][p1 * PSTR],                      \
                            sr[l][p1 * HH + jd], sr[l][p1 * HH + jd + 10],      \
                            oA, oB);                                            \
                    wb[l + 1][p1 * PSTR + jd]      = f2relu(oA);                \
                    wb[l + 1][p1 * PSTR + jd + 10] = f2relu(oB);                \
                }                                                               \
            }                                                                   \
        } else if (is_fc) {                                                     \
            if (STEADY || (unsigned)(tau_ - 12) < TT) {                         \
                logitb[(AA) ^ 1][fc_p][fc_c] = dot20(wA, &rb[LL][fc_p * PSTR],  \
                                                     bjA);                      \
            }                                                                   \
        } else {                                                                \
            if (STEADY || tau_ + 1 < TT) {                                      \
                wb[0][sm_p * PSTR + sm_w] = pk2(xv0, xv1);                      \
            }                                                                   \
            if (STEADY || tau_ + 2 < TT) {                                      \
                xv0 = xf[((tau_ + 2) * BB + xb0) * 2 + sm_w];                   \
                xv1 = xf[((tau_ + 2) * BB + xb1) * 2 + sm_w];                   \
            }                                                                   \
            if (STEADY || (unsigned)(tau_ - 13) < TT) {                         \
                const int t_ = tau_ - 13;                                       \
                ulonglong2 lg = *(const ulonglong2*)&logitb[AA][sm_p][0];       \
                float c0a, c0b, c1a, c1b;                                       \
                unpk(lg.x, c0a, c0b);                                           \
                unpk(lg.y, c1a, c1b);                                           \
                float u0 = sm_w ? c0b : c0a;                                    \
                float u1 = sm_w ? c1b : c1a;                                    \
                float m_ = fmaxf(u0, u1);                                       \
                float lse = m_ + __logf(1.0f + __expf(fminf(u0, u1) - m_));     \
                const int b_ = sm_w ? xb1 : xb0;                                \
                *(float2*)&out[(size_t)(t_ * BB + b_) * 2] =                    \
                    make_float2(u0 - lse, u1 - lse);                            \
            }                                                                   \
        }                                                                       \
        __syncthreads();                                                        \
    } while (0)

    // ---- ramp head: tau 0..STEADY_BEG-1 (generic, runtime parity) ----
#pragma unroll 1
    for (int tau = 0; tau < STEADY_BEG; ++tau) {
        const int A = tau & 1;
        TICK(tau, A, false);
    }

    // ---- steady core: [STEADY_BEG, STEADY_END], parity-unrolled, guard-free ----
    // STEADY_BEG even => first tick parity 0.
#pragma unroll 1
    for (int tau = STEADY_BEG; tau <= STEADY_END; tau += 2) {
        TICK(tau,     0, true);
        TICK(tau + 1, 1, true);
    }

    // ---- tail: STEADY_END+1 .. NTICK-1 (generic) ----
#pragma unroll 1
    for (int tau = STEADY_END + 1; tau < NTICK; ++tau) {
        const int A = tau & 1;
        TICK(tau, A, false);
    }
#undef TICK
}

extern "C" void kernel_launch(void* const* d_in, const int* in_sizes, int n_in,
                              void* d_out, int out_size) {
    const float* x    = (const float*)d_in[0];
    const float* Wih0 = (const float*)d_in[1];
    const float* Wih  = (const float*)d_in[2];
    const float* Whh  = (const float*)d_in[3];
    const float* bih  = (const float*)d_in[4];
    const float* bhh  = (const float*)d_in[5];
    const float* fcw  = (const float*)d_in[6];
    const float* fcb  = (const float*)d_in[7];
    float* out = (float*)d_out;

    rnn_wavefront_kernel<<<NCTA, NTH>>>(x, Wih0, Wih, Whh, bih, bhh, fcw, fcb, out);
}

// round 16
// speedup vs baseline: 1.0418x; 1.0418x over previous
#include <cuda_runtime.h>

// Fused 6-layer ReLU RNN + FC + log_softmax, diagonal-wavefront persistent kernel.
// R16 = R14's thread body (neuron-duo, role split, staged wi partials, broadcast
//       LDS, 40 u64 weight regs) re-packaged as SMALL CTAs: 128 threads / 2
//       batch-pairs, 512 CTAs, 4 CTAs co-resident per SM (launch_bounds(128,4),
//       4 x 16K = 64K regs). Four INDEPENDENT barrier domains per SM: while one
//       CTA waits at __syncthreads(), the other three issue -> fma pipe stays fed.
//       Also uses all 148 SMs (68x4 + 80x3 CTAs) instead of 128.

#define TT 1024
#define BB 2048
#define HH 20
#define LL 6
#define ROWS (LL + 1)  // row 0 = x, row l+1 = h_l
#define PP 2           // batch-pairs per CTA (pair = 2 batch elems packed f32x2)
#define PSTR 22        // padded row stride in 8B units (16B-aligned rows)
#define NTH 128
#define NCTA 512
#define NTICK (TT + 13)

typedef unsigned long long u64;

__device__ __forceinline__ u64 f2fma(u64 a, u64 b, u64 c) {
    u64 r; asm("fma.rn.f32x2 %0, %1, %2, %3;" : "=l"(r) : "l"(a), "l"(b), "l"(c)); return r;
}
__device__ __forceinline__ u64 f2add(u64 a, u64 b) {
    u64 r; asm("add.rn.f32x2 %0, %1, %2;" : "=l"(r) : "l"(a), "l"(b)); return r;
}
__device__ __forceinline__ u64 dup2(float x) {
    u64 r; asm("mov.b64 %0, {%1, %1};" : "=l"(r) : "f"(x)); return r;
}
__device__ __forceinline__ u64 pk2(float lo, float hi) {
    u64 r; asm("mov.b64 %0, {%1, %2};" : "=l"(r) : "f"(lo), "f"(hi)); return r;
}
__device__ __forceinline__ void unpk(u64 a, float& lo, float& hi) {
    asm("mov.b64 {%0, %1}, %2;" : "=f"(lo), "=f"(hi) : "l"(a));
}
__device__ __forceinline__ u64 f2relu(u64 a) {
    float lo, hi; unpk(a, lo, hi);
    return pk2(fmaxf(lo, 0.0f), fmaxf(hi, 0.0f));
}

// Two 20-element f32x2 dots sharing one loaded h-row (neuron duo).
__device__ __forceinline__ void dot20x2(const u64 (&wa)[HH], const u64 (&wb_)[HH],
                                        const u64* hbase, u64 accA, u64 accB,
                                        u64& outA, u64& outB) {
    const ulonglong2* h2 = (const ulonglong2*)hbase;
    u64 aA0 = accA, aA1 = 0ull, aB0 = accB, aB1 = 0ull;
#pragma unroll
    for (int q = 0; q < 10; q++) {
        ulonglong2 hq = h2[q];
        aA0 = f2fma(wa[2 * q],     hq.x, aA0);
        aA1 = f2fma(wa[2 * q + 1], hq.y, aA1);
        aB0 = f2fma(wb_[2 * q],     hq.x, aB0);
        aB1 = f2fma(wb_[2 * q + 1], hq.y, aB1);
    }
    outA = f2add(aA0, aA1);
    outB = f2add(aB0, aB1);
}

// Single 20-element dot (fc lanes).
__device__ __forceinline__ u64 dot20(const u64 (&w)[HH], const u64* hbase, u64 acc) {
    const ulonglong2* h2 = (const ulonglong2*)hbase;
    u64 a0 = acc, a1 = 0ull;
#pragma unroll
    for (int q = 0; q < 10; q++) {
        ulonglong2 hq = h2[q];
        a0 = f2fma(w[2 * q],     hq.x, a0);
        a1 = f2fma(w[2 * q + 1], hq.y, a1);
    }
    return f2add(a0, a1);
}

__global__ __launch_bounds__(NTH, 4) void rnn_wavefront_kernel(
    const float* __restrict__ x,     // [T, B, 2]
    const float* __restrict__ Wih0,  // [H, 2]
    const float* __restrict__ Wih,   // [L-1, H, H]
    const float* __restrict__ Whh,   // [L, H, H]
    const float* __restrict__ bih,   // [L, H]
    const float* __restrict__ bhh,   // [L, H]
    const float* __restrict__ fcw,   // [2, H]
    const float* __restrict__ fcb,   // [2]
    float* __restrict__ out)         // [T, B, 2]
{
    __shared__ __align__(16) u64 hb[2][ROWS][PP * PSTR];  // x + h state, double-buffered
    __shared__ __align__(16) u64 st[2][LL][PP * HH];      // staged wi partials
    __shared__ __align__(16) u64 logitb[2][PP][2];        // logits, double-buffered

    const int tid = threadIdx.x;

    for (int i = tid; i < 2 * ROWS * PP * PSTR; i += NTH) ((u64*)hb)[i] = 0ull;
    for (int i = tid; i < 2 * LL * PP * HH; i += NTH)     ((u64*)st)[i] = 0ull;
    for (int i = tid; i < 2 * PP * 2; i += NTH)           ((u64*)logitb)[i] = 0ull;

    // ---- role decomposition ----
    // layer lanes: tid = role*60 + l*10 + jd  (0..119); each handles BOTH pairs.
    const bool is_layer = tid < 120;
    const int role = tid / 60;           // 0 = wi-dot (stage), 1 = wh-dot (relu+store)
    const int sub  = tid % 60;
    const int l    = sub / 10;
    const int jd   = sub % 10;           // neuron duo: j = jd, jd+10

    const bool is_fc = (tid >= 120) && (tid < 124);     // fc lanes
    const int fc_p = (tid - 120) >> 1;
    const int fc_c = tid & 1;
    const int sm_p = (tid - 124) >> 1;                  // sm/x lanes 124..127
    const int sm_w = tid & 1;

    // ---- weights into registers: rows for neurons jd and jd+10 ----
    u64 wA[HH], wB[HH];
    u64 bjA = 0ull, bjB = 0ull;
#pragma unroll
    for (int k = 0; k < HH; k++) { wA[k] = 0ull; wB[k] = 0ull; }

    if (is_layer) {
        if (role == 1) {          // wh: recurrent weights
#pragma unroll
            for (int k = 0; k < HH; k++) {
                wA[k] = dup2(Whh[(l * HH + jd) * HH + k]);
                wB[k] = dup2(Whh[(l * HH + jd + 10) * HH + k]);
            }
        } else if (l > 0) {       // wi: input weights, generic layer
#pragma unroll
            for (int k = 0; k < HH; k++) {
                wA[k] = dup2(Wih[((l - 1) * HH + jd) * HH + k]);
                wB[k] = dup2(Wih[((l - 1) * HH + jd + 10) * HH + k]);
            }
            bjA = dup2(bih[l * HH + jd] + bhh[l * HH + jd]);
            bjB = dup2(bih[l * HH + jd + 10] + bhh[l * HH + jd + 10]);
        } else {                  // wi layer 0: x-projection in slots 0..1
            wA[0] = dup2(Wih0[jd * 2 + 0]);
            wA[1] = dup2(Wih0[jd * 2 + 1]);
            wB[0] = dup2(Wih0[(jd + 10) * 2 + 0]);
            wB[1] = dup2(Wih0[(jd + 10) * 2 + 1]);
            bjA = dup2(bih[jd] + bhh[jd]);
            bjB = dup2(bih[jd + 10] + bhh[jd + 10]);
        }
    } else if (is_fc) {
#pragma unroll
        for (int k = 0; k < HH; k++) wA[k] = dup2(fcw[fc_c * HH + k]);
        bjA = dup2(fcb[fc_c]);
    }

    // ---- x prefetch state (sm lanes; 2-tick register pipeline) ----
    const float* __restrict__ xf = (const float*)x;   // xf[(t*BB + b)*2 + k]
    int xb0 = 0, xb1 = 0;
    float xv0 = 0.0f, xv1 = 0.0f;
    if (tid >= 124) {
        xb0 = blockIdx.x * PP + sm_p;
        xb1 = xb0 + (BB / 2);
        hb[0][0][sm_p * PSTR + sm_w] = pk2(xf[xb0 * 2 + sm_w], xf[xb1 * 2 + sm_w]);
        xv0 = xf[(BB + xb0) * 2 + sm_w];
        xv1 = xf[(BB + xb1) * 2 + sm_w];
    }

    __syncthreads();

    for (int tau = 0; tau < NTICK; ++tau) {
        const int A = tau & 1;
        const u64(*rb)[PP * PSTR] = hb[A];       // read buffer (written last tick)
        u64(*wb)[PP * PSTR] = hb[A ^ 1];         // write buffer (this tick)
        const u64(*sr)[PP * HH] = st[A];         // staged wi (last tick)
        u64(*sw)[PP * HH] = st[A ^ 1];           // staged wi (this tick)

        if (is_layer) {
            if (role == 0) {
                // wi(t1) = Wih_l * h_{l-1}(t1) + b,  t1 = tau - 2l
                if ((unsigned)(tau - 2 * l) < TT) {
                    u64 oA, oB;
                    dot20x2(wA, wB, &rb[l][0 * PSTR], bjA, bjB, oA, oB);
                    sw[l][0 * HH + jd]      = oA;
                    sw[l][0 * HH + jd + 10] = oB;
                    dot20x2(wA, wB, &rb[l][1 * PSTR], bjA, bjB, oA, oB);
                    sw[l][1 * HH + jd]      = oA;
                    sw[l][1 * HH + jd + 10] = oB;
                }
            } else {
                // h_l(t0) = relu(Whh_l * h_l(t0-1) + staged wi(t0)), t0 = tau - 2l - 1
                if ((unsigned)(tau - 2 * l - 1) < TT) {
                    u64 oA, oB;
                    dot20x2(wA, wB, &rb[l + 1][0 * PSTR],
                            sr[l][0 * HH + jd], sr[l][0 * HH + jd + 10], oA, oB);
                    wb[l + 1][0 * PSTR + jd]      = f2relu(oA);
                    wb[l + 1][0 * PSTR + jd + 10] = f2relu(oB);
                    dot20x2(wA, wB, &rb[l + 1][1 * PSTR],
                            sr[l][1 * HH + jd], sr[l][1 * HH + jd + 10], oA, oB);
                    wb[l + 1][1 * PSTR + jd]      = f2relu(oA);
                    wb[l + 1][1 * PSTR + jd + 10] = f2relu(oB);
                }
            }
        } else if (is_fc) {
            // logits(t = tau - 12) from h_5 (row 6)
            if ((unsigned)(tau - 12) < TT) {
                logitb[A ^ 1][fc_p][fc_c] = dot20(wA, &rb[LL][fc_p * PSTR], bjA);
            }
        } else {
            // ---- x duty: stage x(tau+1) from regs, prefetch x(tau+2) ----
            if (tau + 1 < TT) {
                wb[0][sm_p * PSTR + sm_w] = pk2(xv0, xv1);
            }
            if (tau + 2 < TT) {
                xv0 = xf[((tau + 2) * BB + xb0) * 2 + sm_w];
                xv1 = xf[((tau + 2) * BB + xb1) * 2 + sm_w];
            }
            // ---- log_softmax + store, t = tau - 13 ----
            if ((unsigned)(tau - 13) < TT) {
                const int t = tau - 13;
                ulonglong2 lg = *(const ulonglong2*)&logitb[A][sm_p][0];
                float c0a, c0b, c1a, c1b;
                unpk(lg.x, c0a, c0b);   // class-0 logits for (b0, b1)
                unpk(lg.y, c1a, c1b);   // class-1 logits
                float u0 = sm_w ? c0b : c0a;
                float u1 = sm_w ? c1b : c1a;
                float m = fmaxf(u0, u1);
                float lse = m + __logf(1.0f + __expf(fminf(u0, u1) - m));
                const int b = sm_w ? xb1 : xb0;
                *(float2*)&out[(size_t)(t * BB + b) * 2] = make_float2(u0 - lse, u1 - lse);
            }
        }

        __syncthreads();
    }
}

extern "C" void kernel_launch(void* const* d_in, const int* in_sizes, int n_in,
                              void* d_out, int out_size) {
    const float* x    = (const float*)d_in[0];
    const float* Wih0 = (const float*)d_in[1];
    const float* Wih  = (const float*)d_in[2];
    const float* Whh  = (const float*)d_in[3];
    const float* bih  = (const float*)d_in[4];
    const float* bhh  = (const float*)d_in[5];
    const float* fcw  = (const float*)d_in[6];
    const float* fcb  = (const float*)d_in[7];
    float* out = (float*)d_out;

    rnn_wavefront_kernel<<<NCTA, NTH>>>(x, Wih0, Wih, Whh, bih, bhh, fcw, fcb, out);
}